// round 14
// baseline (speedup 1.0000x reference)
#include <cuda_runtime.h>

#define BB     2048
#define NCTX   64
#define ZD     64
#define RD     128
#define HD     128
#define NSTEPS 20
#define DT     0.05f
#define DIFF   0.3162277660168379f

typedef unsigned long long u64;

__device__ float g_r[BB * RD];
__device__ float g_grad[BB * ZD];

__device__ __forceinline__ float sigf(float x) { return 1.0f / (1.0f + __expf(-x)); }
__device__ __forceinline__ u64 pk2(float x, float y) {
    u64 r; asm("mov.b64 %0, {%1, %2};" : "=l"(r) : "f"(x), "f"(y)); return r;
}
__device__ __forceinline__ void up2(u64 v, float& x, float& y) {
    asm("mov.b64 {%0, %1}, %2;" : "=f"(x), "=f"(y) : "l"(v));
}
__device__ __forceinline__ void fma2(u64& d, u64 a, u64 b) {
    asm("fma.rn.f32x2 %0, %1, %2, %0;" : "+l"(d) : "l"(a), "l"(b));
}

// ---------------- Encoder (unchanged, runs once) ----------------
__global__ void __launch_bounds__(128, 1) encoder_kernel(
    const float* __restrict__ x_ctx, const float* __restrict__ y_ctx,
    const float* __restrict__ mask,
    const float* __restrict__ We1, const float* __restrict__ be1,
    const float* __restrict__ We2, const float* __restrict__ be2,
    const float* __restrict__ We3, const float* __restrict__ be3)
{
    extern __shared__ float sm[];
    float4* h1s  = (float4*)sm;
    float4* h2s  = h1s + 128;
    float*  We2s = (float*)(h2s + 128);
    float*  We3s = We2s + HD * HD;
    float*  xs   = We3s + HD * HD;
    float*  ys   = xs + 128;
    float*  ms   = ys + 64;

    const int tid = threadIdx.x;
    {
        const float4* A4 = (const float4*)We2;
        const float4* B4 = (const float4*)We3;
        float4* S4 = (float4*)We2s;
        float4* T4 = (float4*)We3s;
        for (int i = tid; i < HD * HD / 4; i += 128) { S4[i] = A4[i]; T4[i] = B4[i]; }
    }
    const float w10 = We1[tid], w11 = We1[HD + tid], w12 = We1[2 * HD + tid];
    const float b1 = be1[tid], b2 = be2[tid], b3 = be3[tid];
    __syncthreads();

    for (int b = blockIdx.x; b < BB; b += gridDim.x) {
        xs[tid] = x_ctx[b * (NCTX * 2) + tid];
        if (tid < NCTX) { ys[tid] = y_ctx[b * NCTX + tid]; ms[tid] = mask[b * NCTX + tid]; }
        __syncthreads();

        float racc = 0.0f;
        #pragma unroll 1
        for (int it = 0; it < NCTX / 4; ++it) {
            const int n0 = it * 4;
            float4 h1;
            float* hp = (float*)&h1;
            #pragma unroll
            for (int q = 0; q < 4; ++q) {
                const int n = n0 + q;
                float p = b1 + xs[2 * n] * w10 + xs[2 * n + 1] * w11 + ys[n] * w12;
                hp[q] = p * sigf(p);
            }
            h1s[tid] = h1;
            __syncthreads();

            float a0 = b2, a1 = b2, a2 = b2, a3 = b2;
            #pragma unroll 8
            for (int k = 0; k < HD; ++k) {
                float4 hh = h1s[k];
                float  w  = We2s[k * HD + tid];
                a0 = fmaf(hh.x, w, a0); a1 = fmaf(hh.y, w, a1);
                a2 = fmaf(hh.z, w, a2); a3 = fmaf(hh.w, w, a3);
            }
            float4 h2;
            h2.x = a0 * sigf(a0); h2.y = a1 * sigf(a1);
            h2.z = a2 * sigf(a2); h2.w = a3 * sigf(a3);
            h2s[tid] = h2;
            __syncthreads();

            a0 = b3; a1 = b3; a2 = b3; a3 = b3;
            #pragma unroll 8
            for (int k = 0; k < HD; ++k) {
                float4 hh = h2s[k];
                float  w  = We3s[k * HD + tid];
                a0 = fmaf(hh.x, w, a0); a1 = fmaf(hh.y, w, a1);
                a2 = fmaf(hh.z, w, a2); a3 = fmaf(hh.w, w, a3);
            }
            racc = fmaf(a0, ms[n0 + 0], racc);
            racc = fmaf(a1, ms[n0 + 1], racc);
            racc = fmaf(a2, ms[n0 + 2], racc);
            racc = fmaf(a3, ms[n0 + 3], racc);
        }
        float msum = 0.0f;
        #pragma unroll
        for (int n = 0; n < NCTX; ++n) msum += ms[n];
        g_r[b * RD + tid] = racc / fmaxf(msum, 1e-6f);
        __syncthreads();
    }
}

// ---------------- Grad kernel: 14 warp-groups, 4 cols/lane, warp-sync ----------------
#define GPB   14
#define GSZ   1984

__global__ void __launch_bounds__(448, 1) grad_kernel(
    const float* __restrict__ z, const float* __restrict__ x_ctx,
    const float* __restrict__ y_ctx, const float* __restrict__ mask,
    const float* __restrict__ Wd1, const float* __restrict__ bd1,
    const float* __restrict__ Wd2, const float* __restrict__ bd2,
    const float* __restrict__ Wd3, const float* __restrict__ bd3,
    float t)
{
    extern __shared__ float sm[];
    float* Wd1p  = sm;                       // 66*129
    float* Wd2p  = Wd1p + 66 * 129;          // 128*129
    float* gbase = Wd2p + 128 * 129 + 2;     // 16B aligned

    const int tidb = threadIdx.x;
    const int grp  = tidb >> 5;
    const int lane = tidb & 31;

    float* gb  = gbase + grp * GSZ;
    float* h1T = gb;             // 128 rows x stride 12 (h1, reused for dpre2)
    float* xs  = gb + 1536;
    float* ys  = xs + 128;
    float* ms  = ys + 64;
    float* zsh = ms + 64;
    float* ds  = zsh + 64;

    for (int i = tidb; i < 66 * HD; i += 448) {
        int r = i >> 7, c = i & 127;
        Wd1p[r * 129 + c] = Wd1[i];
    }
    for (int i = tidb; i < HD * HD; i += 448) {
        int r = i >> 7, c = i & 127;
        Wd2p[r * 129 + c] = Wd2[i];
    }
    float b1c[4], b2c[4], w3c[4];
    #pragma unroll
    for (int q = 0; q < 4; ++q) {
        b1c[q] = bd1[lane + 32 * q];
        b2c[q] = bd2[lane + 32 * q];
        w3c[q] = Wd3[lane + 32 * q];
    }
    const float bd3v = bd3[0];
    __syncthreads();

    float wx0[4], wx1[4];
    #pragma unroll
    for (int q = 0; q < 4; ++q) {
        wx0[q] = Wd1p[64 * 129 + lane + 32 * q];
        wx1[q] = Wd1p[65 * 129 + lane + 32 * q];
    }

    const int b = blockIdx.x * GPB + grp;
    if (b < BB) {
        zsh[lane]      = z[b * ZD + lane];
        zsh[lane + 32] = z[b * ZD + lane + 32];
        #pragma unroll
        for (int i = 0; i < 4; ++i) xs[lane + 32 * i] = x_ctx[b * (NCTX * 2) + lane + 32 * i];
        ys[lane] = y_ctx[b * NCTX + lane];      ys[lane + 32] = y_ctx[b * NCTX + lane + 32];
        ms[lane] = mask[b * NCTX + lane];       ms[lane + 32] = mask[b * NCTX + lane + 32];
        __syncwarp();

        float pre1[4] = { b1c[0], b1c[1], b1c[2], b1c[3] };
        #pragma unroll 8
        for (int k = 0; k < ZD; ++k) {
            const float zk = zsh[k];
            #pragma unroll
            for (int q = 0; q < 4; ++q)
                pre1[q] = fmaf(zk, Wd1p[k * 129 + lane + 32 * q], pre1[q]);
        }

        float dps[4] = { 0.0f, 0.0f, 0.0f, 0.0f };
        if (t > 0.0f) {
            #pragma unroll 1
            for (int it = 0; it < NCTX / 8; ++it) {
                const int n0 = it * 8;
                float sd[4][8];
                #pragma unroll
                for (int q = 0; q < 4; ++q) {
                    float hv[8];
                    #pragma unroll
                    for (int n = 0; n < 8; ++n) {
                        const float xa = xs[2 * (n0 + n)], xb = xs[2 * (n0 + n) + 1];
                        const float p = fmaf(xa, wx0[q], fmaf(xb, wx1[q], pre1[q]));
                        const float s = sigf(p);
                        hv[n] = p * s;
                        sd[q][n] = s * (1.0f + p * (1.0f - s));
                    }
                    *(float4*)&h1T[(lane + 32 * q) * 12]     = make_float4(hv[0], hv[1], hv[2], hv[3]);
                    *(float4*)&h1T[(lane + 32 * q) * 12 + 4] = make_float4(hv[4], hv[5], hv[6], hv[7]);
                }
                __syncwarp();                               // A: h1 visible

                u64 acc[4][4];
                #pragma unroll
                for (int q = 0; q < 4; ++q)
                    #pragma unroll
                    for (int p = 0; p < 4; ++p) acc[q][p] = pk2(b2c[q], b2c[q]);
                #pragma unroll 4
                for (int k = 0; k < HD; ++k) {
                    const u64 h0  = *(const u64*)&h1T[k * 12];
                    const u64 h1p = *(const u64*)&h1T[k * 12 + 2];
                    const u64 h2p = *(const u64*)&h1T[k * 12 + 4];
                    const u64 h3p = *(const u64*)&h1T[k * 12 + 6];
                    #pragma unroll
                    for (int q = 0; q < 4; ++q) {
                        const float w = Wd2p[k * 129 + lane + 32 * q];
                        const u64 wd = pk2(w, w);
                        fma2(acc[q][0], wd, h0);  fma2(acc[q][1], wd, h1p);
                        fma2(acc[q][2], wd, h2p); fma2(acc[q][3], wd, h3p);
                    }
                }
                float a[4][8], tder[4][8], part[8];
                #pragma unroll
                for (int n = 0; n < 8; ++n) part[n] = 0.0f;
                #pragma unroll
                for (int q = 0; q < 4; ++q) {
                    #pragma unroll
                    for (int p = 0; p < 4; ++p) up2(acc[q][p], a[q][2 * p], a[q][2 * p + 1]);
                    #pragma unroll
                    for (int n = 0; n < 8; ++n) {
                        const float s = sigf(a[q][n]);
                        part[n] = fmaf(a[q][n] * s, w3c[q], part[n]);
                        tder[q][n] = s * (1.0f + a[q][n] * (1.0f - s));
                    }
                }
                #pragma unroll
                for (int off = 16; off; off >>= 1) {
                    #pragma unroll
                    for (int n = 0; n < 8; ++n)
                        part[n] += __shfl_xor_sync(0xffffffffu, part[n], off);
                }
                float e[8];
                #pragma unroll
                for (int n = 0; n < 8; ++n)
                    e[n] = -t * (ys[n0 + n] - (part[n] + bd3v)) * ms[n0 + n];
                __syncwarp();                               // B: fwd reads done
                #pragma unroll
                for (int q = 0; q < 4; ++q) {
                    float dv[8];
                    #pragma unroll
                    for (int n = 0; n < 8; ++n) dv[n] = e[n] * w3c[q] * tder[q][n];
                    *(float4*)&h1T[(lane + 32 * q) * 12]     = make_float4(dv[0], dv[1], dv[2], dv[3]);
                    *(float4*)&h1T[(lane + 32 * q) * 12 + 4] = make_float4(dv[4], dv[5], dv[6], dv[7]);
                }
                __syncwarp();                               // C: dpre2 visible

                u64 bc[4][4];
                #pragma unroll
                for (int q = 0; q < 4; ++q)
                    #pragma unroll
                    for (int p = 0; p < 4; ++p) bc[q][p] = 0ull;
                #pragma unroll 4
                for (int k = 0; k < HD; ++k) {
                    const u64 d0 = *(const u64*)&h1T[k * 12];
                    const u64 d1 = *(const u64*)&h1T[k * 12 + 2];
                    const u64 d2 = *(const u64*)&h1T[k * 12 + 4];
                    const u64 d3 = *(const u64*)&h1T[k * 12 + 6];
                    #pragma unroll
                    for (int q = 0; q < 4; ++q) {
                        const float w = Wd2p[(lane + 32 * q) * 129 + k];   // W2^T
                        const u64 wd = pk2(w, w);
                        fma2(bc[q][0], wd, d0); fma2(bc[q][1], wd, d1);
                        fma2(bc[q][2], wd, d2); fma2(bc[q][3], wd, d3);
                    }
                }
                #pragma unroll
                for (int q = 0; q < 4; ++q)
                    #pragma unroll
                    for (int p = 0; p < 4; ++p) {
                        float u, v;
                        up2(bc[q][p], u, v);
                        dps[q] = fmaf(u, sd[q][2 * p], dps[q]);
                        dps[q] = fmaf(v, sd[q][2 * p + 1], dps[q]);
                    }
                __syncwarp();                               // D: h1T reuse next tile
            }
        }
        #pragma unroll
        for (int q = 0; q < 4; ++q) ds[lane + 32 * q] = dps[q];
        __syncwarp();
        {
            float acc0 = 0.0f, acc1 = 0.0f;
            #pragma unroll 8
            for (int j = 0; j < HD; ++j) {
                const float dj = ds[j];
                acc0 = fmaf(dj, Wd1p[lane * 129 + j], acc0);
                acc1 = fmaf(dj, Wd1p[(lane + 32) * 129 + j], acc1);
            }
            float g0 = zsh[lane] + acc0;
            float g1 = zsh[lane + 32] + acc1;
            g0 = fminf(fmaxf(g0, -100.0f), 100.0f);
            g1 = fminf(fmaxf(g1, -100.0f), 100.0f);
            g_grad[b * ZD + lane]      = g0;
            g_grad[b * ZD + lane + 32] = g1;
        }
    }
}

// ---------------- Drift + z update: 256 thr = 2 halves x 4 b, float4 fills ----------------
__global__ void __launch_bounds__(256, 1) drift_kernel(
    float* __restrict__ z, const float* __restrict__ noise,
    const float* __restrict__ Wf1, const float* __restrict__ bf1,
    const float* __restrict__ Wf2, const float* __restrict__ bf2,
    const float* __restrict__ Wf3, const float* __restrict__ bf3,
    float t)
{
    extern __shared__ float sm[];
    float*  Wf1s = sm;                        // 193*128 = 24704
    float*  Wf2s = Wf1s + 193 * HD;           // 16384
    float*  Wf3s = Wf2s + HD * HD;            // 8192
    float4* f1sT = (float4*)(Wf3s + HD * ZD); // 2 x 128 f4
    float4* f2sT = f1sT + 256;                // 2 x 128 f4
    float4* zshT = f2sT + 256;                // 2 x 64 f4
    float4* rshT = zshT + 128;                // 2 x 128 f4

    const int tid  = threadIdx.x;
    const int half = tid >> 7;
    const int tloc = tid & 127;
    {
        const float4* A4 = (const float4*)Wf1;
        const float4* B4 = (const float4*)Wf2;
        const float4* C4 = (const float4*)Wf3;
        float4* S1 = (float4*)Wf1s; float4* S2 = (float4*)Wf2s; float4* S3 = (float4*)Wf3s;
        for (int i = tid; i < 193 * HD / 4; i += 256) S1[i] = A4[i];
        for (int i = tid; i < HD * HD / 4; i += 256)  S2[i] = B4[i];
        for (int i = tid; i < HD * ZD / 4; i += 256)  S3[i] = C4[i];
    }
    const float b1 = bf1[tloc], b2 = bf2[tloc];
    const float bf3v = bf3[tloc & 63];
    __syncthreads();
    const float wt = Wf1s[192 * HD + tloc];
    const int kk = tloc & 63, g2 = tloc >> 6;

    float4* f1h = f1sT + half * 128;
    float4* f2h = f2sT + half * 128;
    float4* zsh = zshT + half * 64;
    float4* rsh = rshT + half * 128;

    for (int b0 = blockIdx.x * 8; b0 < BB; b0 += gridDim.x * 8) {
        const int bq = b0 + 4 * half;     // this half's quad base
        float* zf = (float*)zsh;
        float* rf = (float*)rsh;
        #pragma unroll
        for (int i = tloc; i < 4 * ZD; i += 128) {
            int q = i >> 6, k = i & 63;
            zf[k * 4 + q] = z[(bq + q) * ZD + k];
        }
        #pragma unroll
        for (int i = tloc; i < 4 * RD; i += 128) {
            int q = i >> 7, k = i & 127;
            rf[k * 4 + q] = g_r[(bq + q) * RD + k];
        }
        __syncthreads();

        const float pb = fmaf(t, wt, b1);
        float p0 = pb, p1 = pb, p2 = pb, p3 = pb;
        #pragma unroll 8
        for (int k = 0; k < ZD; ++k) {
            const float w = Wf1s[k * HD + tloc];
            const float4 v = zsh[k];
            p0 = fmaf(v.x, w, p0); p1 = fmaf(v.y, w, p1);
            p2 = fmaf(v.z, w, p2); p3 = fmaf(v.w, w, p3);
        }
        #pragma unroll 8
        for (int k = 0; k < RD; ++k) {
            const float w = Wf1s[(ZD + k) * HD + tloc];
            const float4 v = rsh[k];
            p0 = fmaf(v.x, w, p0); p1 = fmaf(v.y, w, p1);
            p2 = fmaf(v.z, w, p2); p3 = fmaf(v.w, w, p3);
        }
        f1h[tloc] = make_float4(p0 * sigf(p0), p1 * sigf(p1), p2 * sigf(p2), p3 * sigf(p3));
        __syncthreads();

        p0 = b2; p1 = b2; p2 = b2; p3 = b2;
        #pragma unroll 8
        for (int k = 0; k < HD; ++k) {
            const float w = Wf2s[k * HD + tloc];
            const float4 v = f1h[k];
            p0 = fmaf(v.x, w, p0); p1 = fmaf(v.y, w, p1);
            p2 = fmaf(v.z, w, p2); p3 = fmaf(v.w, w, p3);
        }
        f2h[tloc] = make_float4(p0 * sigf(p0), p1 * sigf(p1), p2 * sigf(p2), p3 * sigf(p3));
        __syncthreads();

        float accA = 0.0f, accB = 0.0f;
        #pragma unroll 8
        for (int j = 0; j < HD; ++j) {
            const float w = Wf3s[j * ZD + kk];
            const float4 v = f2h[j];
            const float vA = g2 ? v.y : v.x;
            const float vB = g2 ? v.w : v.z;
            accA = fmaf(vA, w, accA);
            accB = fmaf(vB, w, accB);
        }
        {
            const int qA = g2, qB = g2 + 2;
            const int bA = bq + qA, bB = bq + qB;
            z[bA * ZD + kk] = zf[kk * 4 + qA]
                + (bf3v + accA - g_grad[bA * ZD + kk]) * DT
                + DIFF * noise[bA * ZD + kk];
            z[bB * ZD + kk] = zf[kk * 4 + qB]
                + (bf3v + accB - g_grad[bB * ZD + kk]) * DT
                + DIFF * noise[bB * ZD + kk];
        }
        __syncthreads();
    }
}

// ---------------------------------------------------------------------------
extern "C" void kernel_launch(void* const* d_in, const int* in_sizes, int n_in,
                              void* d_out, int out_size)
{
    const float* x_ctx  = (const float*)d_in[0];
    const float* y_ctx  = (const float*)d_in[1];
    const float* mask   = (const float*)d_in[2];
    const float* z0     = (const float*)d_in[3];
    const float* noises = (const float*)d_in[4];
    const float* We1 = (const float*)d_in[5];  const float* be1 = (const float*)d_in[6];
    const float* We2 = (const float*)d_in[7];  const float* be2 = (const float*)d_in[8];
    const float* We3 = (const float*)d_in[9];  const float* be3 = (const float*)d_in[10];
    const float* Wd1 = (const float*)d_in[11]; const float* bd1 = (const float*)d_in[12];
    const float* Wd2 = (const float*)d_in[13]; const float* bd2 = (const float*)d_in[14];
    const float* Wd3 = (const float*)d_in[15]; const float* bd3 = (const float*)d_in[16];
    const float* Wf1 = (const float*)d_in[17]; const float* bf1 = (const float*)d_in[18];
    const float* Wf2 = (const float*)d_in[19]; const float* bf2 = (const float*)d_in[20];
    const float* Wf3 = (const float*)d_in[21]; const float* bf3 = (const float*)d_in[22];
    float* z = (float*)d_out;

    const size_t smE = (size_t)(512 + 512 + 16384 + 16384 + 128 + 64 + 64) * 4;
    const size_t smG = (size_t)(66 * 129 + 128 * 129 + 2 + GPB * GSZ) * 4;
    const size_t smF = (size_t)(193 * 128 + 128 * 128 + 128 * 64
                                + 2 * (512 + 512 + 256 + 512)) * 4;

    cudaFuncSetAttribute(encoder_kernel, cudaFuncAttributeMaxDynamicSharedMemorySize, (int)smE);
    cudaFuncSetAttribute(grad_kernel,    cudaFuncAttributeMaxDynamicSharedMemorySize, (int)smG);
    cudaFuncSetAttribute(drift_kernel,   cudaFuncAttributeMaxDynamicSharedMemorySize, (int)smF);

    cudaMemcpyAsync(z, z0, (size_t)BB * ZD * sizeof(float), cudaMemcpyDeviceToDevice);
    encoder_kernel<<<148, 128, smE>>>(x_ctx, y_ctx, mask, We1, be1, We2, be2, We3, be3);

    for (int s = 0; s < NSTEPS; ++s) {
        const float t = (float)s * DT;
        grad_kernel<<<147, 448, smG>>>(z, x_ctx, y_ctx, mask,
                                       Wd1, bd1, Wd2, bd2, Wd3, bd3, t);
        drift_kernel<<<148, 256, smF>>>(z, noises + (size_t)s * BB * ZD,
                                        Wf1, bf1, Wf2, bf2, Wf3, bf3, t);
    }
}

// round 15
// speedup vs baseline: 1.6301x; 1.6301x over previous
#include <cuda_runtime.h>

#define BB     2048
#define NCTX   64
#define ZD     64
#define RD     128
#define HD     128
#define NSTEPS 20
#define DT     0.05f
#define DIFF   0.3162277660168379f

typedef unsigned long long u64;

__device__ float g_r[BB * RD];
__device__ float g_grad[BB * ZD];

__device__ __forceinline__ float sigf(float x) { return 1.0f / (1.0f + __expf(-x)); }
__device__ __forceinline__ u64 pk2(float x, float y) {
    u64 r; asm("mov.b64 %0, {%1, %2};" : "=l"(r) : "f"(x), "f"(y)); return r;
}
__device__ __forceinline__ void up2(u64 v, float& x, float& y) {
    asm("mov.b64 {%0, %1}, %2;" : "=f"(x), "=f"(y) : "l"(v));
}
__device__ __forceinline__ void fma2(u64& d, u64 a, u64 b) {
    asm("fma.rn.f32x2 %0, %1, %2, %0;" : "+l"(d) : "l"(a), "l"(b));
}

// ---------------- Encoder (runs once) ----------------
__global__ void __launch_bounds__(128, 1) encoder_kernel(
    const float* __restrict__ x_ctx, const float* __restrict__ y_ctx,
    const float* __restrict__ mask,
    const float* __restrict__ We1, const float* __restrict__ be1,
    const float* __restrict__ We2, const float* __restrict__ be2,
    const float* __restrict__ We3, const float* __restrict__ be3)
{
    extern __shared__ float sm[];
    float4* h1s  = (float4*)sm;
    float4* h2s  = h1s + 128;
    float*  We2s = (float*)(h2s + 128);
    float*  We3s = We2s + HD * HD;
    float*  xs   = We3s + HD * HD;
    float*  ys   = xs + 128;
    float*  ms   = ys + 64;

    const int tid = threadIdx.x;
    {
        const float4* A4 = (const float4*)We2;
        const float4* B4 = (const float4*)We3;
        float4* S4 = (float4*)We2s;
        float4* T4 = (float4*)We3s;
        for (int i = tid; i < HD * HD / 4; i += 128) { S4[i] = A4[i]; T4[i] = B4[i]; }
    }
    const float w10 = We1[tid], w11 = We1[HD + tid], w12 = We1[2 * HD + tid];
    const float b1 = be1[tid], b2 = be2[tid], b3 = be3[tid];
    __syncthreads();

    for (int b = blockIdx.x; b < BB; b += gridDim.x) {
        xs[tid] = x_ctx[b * (NCTX * 2) + tid];
        if (tid < NCTX) { ys[tid] = y_ctx[b * NCTX + tid]; ms[tid] = mask[b * NCTX + tid]; }
        __syncthreads();

        float racc = 0.0f;
        #pragma unroll 1
        for (int it = 0; it < NCTX / 4; ++it) {
            const int n0 = it * 4;
            float4 h1;
            float* hp = (float*)&h1;
            #pragma unroll
            for (int q = 0; q < 4; ++q) {
                const int n = n0 + q;
                float p = b1 + xs[2 * n] * w10 + xs[2 * n + 1] * w11 + ys[n] * w12;
                hp[q] = p * sigf(p);
            }
            h1s[tid] = h1;
            __syncthreads();

            float a0 = b2, a1 = b2, a2 = b2, a3 = b2;
            #pragma unroll 8
            for (int k = 0; k < HD; ++k) {
                float4 hh = h1s[k];
                float  w  = We2s[k * HD + tid];
                a0 = fmaf(hh.x, w, a0); a1 = fmaf(hh.y, w, a1);
                a2 = fmaf(hh.z, w, a2); a3 = fmaf(hh.w, w, a3);
            }
            float4 h2;
            h2.x = a0 * sigf(a0); h2.y = a1 * sigf(a1);
            h2.z = a2 * sigf(a2); h2.w = a3 * sigf(a3);
            h2s[tid] = h2;
            __syncthreads();

            a0 = b3; a1 = b3; a2 = b3; a3 = b3;
            #pragma unroll 8
            for (int k = 0; k < HD; ++k) {
                float4 hh = h2s[k];
                float  w  = We3s[k * HD + tid];
                a0 = fmaf(hh.x, w, a0); a1 = fmaf(hh.y, w, a1);
                a2 = fmaf(hh.z, w, a2); a3 = fmaf(hh.w, w, a3);
            }
            racc = fmaf(a0, ms[n0 + 0], racc);
            racc = fmaf(a1, ms[n0 + 1], racc);
            racc = fmaf(a2, ms[n0 + 2], racc);
            racc = fmaf(a3, ms[n0 + 3], racc);
        }
        float msum = 0.0f;
        #pragma unroll
        for (int n = 0; n < NCTX; ++n) msum += ms[n];
        g_r[b * RD + tid] = racc / fmaxf(msum, 1e-6f);
        __syncthreads();
    }
}

// ---------------- Grad kernel: R12-proven body (float4 loads + pk2) ----------------
#define GPB   14
#define GSZ   1984

__global__ void __launch_bounds__(448, 1) grad_kernel(
    const float* __restrict__ z, const float* __restrict__ x_ctx,
    const float* __restrict__ y_ctx, const float* __restrict__ mask,
    const float* __restrict__ Wd1, const float* __restrict__ bd1,
    const float* __restrict__ Wd2, const float* __restrict__ bd2,
    const float* __restrict__ Wd3, const float* __restrict__ bd3,
    float t)
{
    extern __shared__ float sm[];
    float* Wd1p  = sm;                       // 66*129
    float* Wd2p  = Wd1p + 66 * 129;          // 128*129
    float* gbase = Wd2p + 128 * 129 + 2;     // 16B aligned

    const int tidb = threadIdx.x;
    const int grp  = tidb >> 5;
    const int lane = tidb & 31;

    float* gb  = gbase + grp * GSZ;
    float* h1T = gb;             // 128 rows x stride 12 (h1, reused for dpre2)
    float* xs  = gb + 1536;
    float* ys  = xs + 128;
    float* ms  = ys + 64;
    float* zsh = ms + 64;
    float* ds  = zsh + 64;

    for (int i = tidb; i < 66 * HD; i += 448) {
        int r = i >> 7, c = i & 127;
        Wd1p[r * 129 + c] = Wd1[i];
    }
    for (int i = tidb; i < HD * HD; i += 448) {
        int r = i >> 7, c = i & 127;
        Wd2p[r * 129 + c] = Wd2[i];
    }
    float b1c[4], b2c[4], w3c[4];
    #pragma unroll
    for (int q = 0; q < 4; ++q) {
        b1c[q] = bd1[lane + 32 * q];
        b2c[q] = bd2[lane + 32 * q];
        w3c[q] = Wd3[lane + 32 * q];
    }
    const float bd3v = bd3[0];
    __syncthreads();

    float wx0[4], wx1[4];
    #pragma unroll
    for (int q = 0; q < 4; ++q) {
        wx0[q] = Wd1p[64 * 129 + lane + 32 * q];
        wx1[q] = Wd1p[65 * 129 + lane + 32 * q];
    }

    const int b = blockIdx.x * GPB + grp;
    if (b < BB) {
        zsh[lane]      = z[b * ZD + lane];
        zsh[lane + 32] = z[b * ZD + lane + 32];
        #pragma unroll
        for (int i = 0; i < 4; ++i) xs[lane + 32 * i] = x_ctx[b * (NCTX * 2) + lane + 32 * i];
        ys[lane] = y_ctx[b * NCTX + lane];      ys[lane + 32] = y_ctx[b * NCTX + lane + 32];
        ms[lane] = mask[b * NCTX + lane];       ms[lane + 32] = mask[b * NCTX + lane + 32];
        __syncwarp();

        float pre1[4] = { b1c[0], b1c[1], b1c[2], b1c[3] };
        #pragma unroll 8
        for (int k = 0; k < ZD; ++k) {
            const float zk = zsh[k];
            #pragma unroll
            for (int q = 0; q < 4; ++q)
                pre1[q] = fmaf(zk, Wd1p[k * 129 + lane + 32 * q], pre1[q]);
        }

        float dps[4] = { 0.0f, 0.0f, 0.0f, 0.0f };
        if (t > 0.0f) {
            #pragma unroll 1
            for (int it = 0; it < NCTX / 8; ++it) {
                const int n0 = it * 8;
                float sd[4][8];
                #pragma unroll
                for (int q = 0; q < 4; ++q) {
                    float hv[8];
                    #pragma unroll
                    for (int n = 0; n < 8; ++n) {
                        const float xa = xs[2 * (n0 + n)], xb = xs[2 * (n0 + n) + 1];
                        const float p = fmaf(xa, wx0[q], fmaf(xb, wx1[q], pre1[q]));
                        const float s = sigf(p);
                        hv[n] = p * s;
                        sd[q][n] = s * (1.0f + p * (1.0f - s));
                    }
                    *(float4*)&h1T[(lane + 32 * q) * 12]     = make_float4(hv[0], hv[1], hv[2], hv[3]);
                    *(float4*)&h1T[(lane + 32 * q) * 12 + 4] = make_float4(hv[4], hv[5], hv[6], hv[7]);
                }
                __syncwarp();                               // A: h1 visible

                u64 acc[4][4];
                #pragma unroll
                for (int q = 0; q < 4; ++q)
                    #pragma unroll
                    for (int p = 0; p < 4; ++p) acc[q][p] = pk2(b2c[q], b2c[q]);
                #pragma unroll 4
                for (int k = 0; k < HD; ++k) {
                    const float4 HA = *(const float4*)&h1T[k * 12];
                    const float4 HB = *(const float4*)&h1T[k * 12 + 4];
                    const u64 h0 = pk2(HA.x, HA.y), h1p = pk2(HA.z, HA.w);
                    const u64 h2p = pk2(HB.x, HB.y), h3p = pk2(HB.z, HB.w);
                    #pragma unroll
                    for (int q = 0; q < 4; ++q) {
                        const float w = Wd2p[k * 129 + lane + 32 * q];
                        const u64 wd = pk2(w, w);
                        fma2(acc[q][0], wd, h0);  fma2(acc[q][1], wd, h1p);
                        fma2(acc[q][2], wd, h2p); fma2(acc[q][3], wd, h3p);
                    }
                }
                float a[4][8], tder[4][8], part[8];
                #pragma unroll
                for (int n = 0; n < 8; ++n) part[n] = 0.0f;
                #pragma unroll
                for (int q = 0; q < 4; ++q) {
                    #pragma unroll
                    for (int p = 0; p < 4; ++p) up2(acc[q][p], a[q][2 * p], a[q][2 * p + 1]);
                    #pragma unroll
                    for (int n = 0; n < 8; ++n) {
                        const float s = sigf(a[q][n]);
                        part[n] = fmaf(a[q][n] * s, w3c[q], part[n]);
                        tder[q][n] = s * (1.0f + a[q][n] * (1.0f - s));
                    }
                }
                #pragma unroll
                for (int off = 16; off; off >>= 1) {
                    #pragma unroll
                    for (int n = 0; n < 8; ++n)
                        part[n] += __shfl_xor_sync(0xffffffffu, part[n], off);
                }
                float e[8];
                #pragma unroll
                for (int n = 0; n < 8; ++n)
                    e[n] = -t * (ys[n0 + n] - (part[n] + bd3v)) * ms[n0 + n];
                __syncwarp();                               // B: fwd reads done
                #pragma unroll
                for (int q = 0; q < 4; ++q) {
                    float dv[8];
                    #pragma unroll
                    for (int n = 0; n < 8; ++n) dv[n] = e[n] * w3c[q] * tder[q][n];
                    *(float4*)&h1T[(lane + 32 * q) * 12]     = make_float4(dv[0], dv[1], dv[2], dv[3]);
                    *(float4*)&h1T[(lane + 32 * q) * 12 + 4] = make_float4(dv[4], dv[5], dv[6], dv[7]);
                }
                __syncwarp();                               // C: dpre2 visible

                u64 bc[4][4];
                #pragma unroll
                for (int q = 0; q < 4; ++q)
                    #pragma unroll
                    for (int p = 0; p < 4; ++p) bc[q][p] = 0ull;
                #pragma unroll 4
                for (int k = 0; k < HD; ++k) {
                    const float4 DA = *(const float4*)&h1T[k * 12];
                    const float4 DB = *(const float4*)&h1T[k * 12 + 4];
                    const u64 d0 = pk2(DA.x, DA.y), d1 = pk2(DA.z, DA.w);
                    const u64 d2 = pk2(DB.x, DB.y), d3 = pk2(DB.z, DB.w);
                    #pragma unroll
                    for (int q = 0; q < 4; ++q) {
                        const float w = Wd2p[(lane + 32 * q) * 129 + k];   // W2^T
                        const u64 wd = pk2(w, w);
                        fma2(bc[q][0], wd, d0); fma2(bc[q][1], wd, d1);
                        fma2(bc[q][2], wd, d2); fma2(bc[q][3], wd, d3);
                    }
                }
                #pragma unroll
                for (int q = 0; q < 4; ++q)
                    #pragma unroll
                    for (int p = 0; p < 4; ++p) {
                        float u, v;
                        up2(bc[q][p], u, v);
                        dps[q] = fmaf(u, sd[q][2 * p], dps[q]);
                        dps[q] = fmaf(v, sd[q][2 * p + 1], dps[q]);
                    }
                __syncwarp();                               // D: h1T reuse next tile
            }
        }
        #pragma unroll
        for (int q = 0; q < 4; ++q) ds[lane + 32 * q] = dps[q];
        __syncwarp();
        {
            float acc0 = 0.0f, acc1 = 0.0f;
            #pragma unroll 8
            for (int j = 0; j < HD; ++j) {
                const float dj = ds[j];
                acc0 = fmaf(dj, Wd1p[lane * 129 + j], acc0);
                acc1 = fmaf(dj, Wd1p[(lane + 32) * 129 + j], acc1);
            }
            float g0 = zsh[lane] + acc0;
            float g1 = zsh[lane + 32] + acc1;
            g0 = fminf(fmaxf(g0, -100.0f), 100.0f);
            g1 = fminf(fmaxf(g1, -100.0f), 100.0f);
            g_grad[b * ZD + lane]      = g0;
            g_grad[b * ZD + lane + 32] = g1;
        }
    }
}

// ---------------- Drift + z update: 256 thr = 2 halves x 4 b, float4 fills ----------------
__global__ void __launch_bounds__(256, 1) drift_kernel(
    float* __restrict__ z, const float* __restrict__ noise,
    const float* __restrict__ Wf1, const float* __restrict__ bf1,
    const float* __restrict__ Wf2, const float* __restrict__ bf2,
    const float* __restrict__ Wf3, const float* __restrict__ bf3,
    float t)
{
    extern __shared__ float sm[];
    float*  Wf1s = sm;                        // 193*128
    float*  Wf2s = Wf1s + 193 * HD;
    float*  Wf3s = Wf2s + HD * HD;
    float4* f1sT = (float4*)(Wf3s + HD * ZD); // 2 x 128 f4
    float4* f2sT = f1sT + 256;
    float4* zshT = f2sT + 256;                // 2 x 64 f4
    float4* rshT = zshT + 128;                // 2 x 128 f4

    const int tid  = threadIdx.x;
    const int half = tid >> 7;
    const int tloc = tid & 127;
    {
        const float4* A4 = (const float4*)Wf1;
        const float4* B4 = (const float4*)Wf2;
        const float4* C4 = (const float4*)Wf3;
        float4* S1 = (float4*)Wf1s; float4* S2 = (float4*)Wf2s; float4* S3 = (float4*)Wf3s;
        for (int i = tid; i < 193 * HD / 4; i += 256) S1[i] = A4[i];
        for (int i = tid; i < HD * HD / 4; i += 256)  S2[i] = B4[i];
        for (int i = tid; i < HD * ZD / 4; i += 256)  S3[i] = C4[i];
    }
    const float b1 = bf1[tloc], b2 = bf2[tloc];
    const float bf3v = bf3[tloc & 63];
    __syncthreads();
    const float wt = Wf1s[192 * HD + tloc];
    const int kk = tloc & 63, g2 = tloc >> 6;

    float4* f1h = f1sT + half * 128;
    float4* f2h = f2sT + half * 128;
    float4* zsh = zshT + half * 64;
    float4* rsh = rshT + half * 128;

    for (int b0 = blockIdx.x * 8; b0 < BB; b0 += gridDim.x * 8) {
        const int bq = b0 + 4 * half;
        float* zf = (float*)zsh;
        float* rf = (float*)rsh;
        #pragma unroll
        for (int i = tloc; i < 4 * ZD; i += 128) {
            int q = i >> 6, k = i & 63;
            zf[k * 4 + q] = z[(bq + q) * ZD + k];
        }
        #pragma unroll
        for (int i = tloc; i < 4 * RD; i += 128) {
            int q = i >> 7, k = i & 127;
            rf[k * 4 + q] = g_r[(bq + q) * RD + k];
        }
        __syncthreads();

        const float pb = fmaf(t, wt, b1);
        float p0 = pb, p1 = pb, p2 = pb, p3 = pb;
        #pragma unroll 8
        for (int k = 0; k < ZD; ++k) {
            const float w = Wf1s[k * HD + tloc];
            const float4 v = zsh[k];
            p0 = fmaf(v.x, w, p0); p1 = fmaf(v.y, w, p1);
            p2 = fmaf(v.z, w, p2); p3 = fmaf(v.w, w, p3);
        }
        #pragma unroll 8
        for (int k = 0; k < RD; ++k) {
            const float w = Wf1s[(ZD + k) * HD + tloc];
            const float4 v = rsh[k];
            p0 = fmaf(v.x, w, p0); p1 = fmaf(v.y, w, p1);
            p2 = fmaf(v.z, w, p2); p3 = fmaf(v.w, w, p3);
        }
        f1h[tloc] = make_float4(p0 * sigf(p0), p1 * sigf(p1), p2 * sigf(p2), p3 * sigf(p3));
        __syncthreads();

        p0 = b2; p1 = b2; p2 = b2; p3 = b2;
        #pragma unroll 8
        for (int k = 0; k < HD; ++k) {
            const float w = Wf2s[k * HD + tloc];
            const float4 v = f1h[k];
            p0 = fmaf(v.x, w, p0); p1 = fmaf(v.y, w, p1);
            p2 = fmaf(v.z, w, p2); p3 = fmaf(v.w, w, p3);
        }
        f2h[tloc] = make_float4(p0 * sigf(p0), p1 * sigf(p1), p2 * sigf(p2), p3 * sigf(p3));
        __syncthreads();

        float accA = 0.0f, accB = 0.0f;
        #pragma unroll 8
        for (int j = 0; j < HD; ++j) {
            const float w = Wf3s[j * ZD + kk];
            const float4 v = f2h[j];
            const float vA = g2 ? v.y : v.x;
            const float vB = g2 ? v.w : v.z;
            accA = fmaf(vA, w, accA);
            accB = fmaf(vB, w, accB);
        }
        {
            const int qA = g2, qB = g2 + 2;
            const int bA = bq + qA, bB = bq + qB;
            z[bA * ZD + kk] = zf[kk * 4 + qA]
                + (bf3v + accA - g_grad[bA * ZD + kk]) * DT
                + DIFF * noise[bA * ZD + kk];
            z[bB * ZD + kk] = zf[kk * 4 + qB]
                + (bf3v + accB - g_grad[bB * ZD + kk]) * DT
                + DIFF * noise[bB * ZD + kk];
        }
        __syncthreads();
    }
}

// ---------------------------------------------------------------------------
extern "C" void kernel_launch(void* const* d_in, const int* in_sizes, int n_in,
                              void* d_out, int out_size)
{
    const float* x_ctx  = (const float*)d_in[0];
    const float* y_ctx  = (const float*)d_in[1];
    const float* mask   = (const float*)d_in[2];
    const float* z0     = (const float*)d_in[3];
    const float* noises = (const float*)d_in[4];
    const float* We1 = (const float*)d_in[5];  const float* be1 = (const float*)d_in[6];
    const float* We2 = (const float*)d_in[7];  const float* be2 = (const float*)d_in[8];
    const float* We3 = (const float*)d_in[9];  const float* be3 = (const float*)d_in[10];
    const float* Wd1 = (const float*)d_in[11]; const float* bd1 = (const float*)d_in[12];
    const float* Wd2 = (const float*)d_in[13]; const float* bd2 = (const float*)d_in[14];
    const float* Wd3 = (const float*)d_in[15]; const float* bd3 = (const float*)d_in[16];
    const float* Wf1 = (const float*)d_in[17]; const float* bf1 = (const float*)d_in[18];
    const float* Wf2 = (const float*)d_in[19]; const float* bf2 = (const float*)d_in[20];
    const float* Wf3 = (const float*)d_in[21]; const float* bf3 = (const float*)d_in[22];
    float* z = (float*)d_out;

    const size_t smE = (size_t)(512 + 512 + 16384 + 16384 + 128 + 64 + 64) * 4;
    const size_t smG = (size_t)(66 * 129 + 128 * 129 + 2 + GPB * GSZ) * 4;
    const size_t smF = (size_t)(193 * 128 + 128 * 128 + 128 * 64
                                + 2 * (512 + 512 + 256 + 512)) * 4;

    cudaFuncSetAttribute(encoder_kernel, cudaFuncAttributeMaxDynamicSharedMemorySize, (int)smE);
    cudaFuncSetAttribute(grad_kernel,    cudaFuncAttributeMaxDynamicSharedMemorySize, (int)smG);
    cudaFuncSetAttribute(drift_kernel,   cudaFuncAttributeMaxDynamicSharedMemorySize, (int)smF);

    cudaMemcpyAsync(z, z0, (size_t)BB * ZD * sizeof(float), cudaMemcpyDeviceToDevice);
    encoder_kernel<<<148, 128, smE>>>(x_ctx, y_ctx, mask, We1, be1, We2, be2, We3, be3);

    for (int s = 0; s < NSTEPS; ++s) {
        const float t = (float)s * DT;
        grad_kernel<<<147, 448, smG>>>(z, x_ctx, y_ctx, mask,
                                       Wd1, bd1, Wd2, bd2, Wd3, bd3, t);
        drift_kernel<<<148, 256, smF>>>(z, noises + (size_t)s * BB * ZD,
                                        Wf1, bf1, Wf2, bf2, Wf3, bf3, t);
    }
}

// round 16
// speedup vs baseline: 1.7771x; 1.0902x over previous
#include <cuda_runtime.h>

#define BB     2048
#define NCTX   64
#define ZD     64
#define RD     128
#define HD     128
#define NSTEPS 20
#define DT     0.05f
#define DIFF   0.3162277660168379f

typedef unsigned long long u64;

__device__ float g_r[BB * RD];
__device__ float g_grad[BB * ZD];

__device__ __forceinline__ float sigf(float x) { return 1.0f / (1.0f + __expf(-x)); }
__device__ __forceinline__ u64 pk2(float x, float y) {
    u64 r; asm("mov.b64 %0, {%1, %2};" : "=l"(r) : "f"(x), "f"(y)); return r;
}
__device__ __forceinline__ void up2(u64 v, float& x, float& y) {
    asm("mov.b64 {%0, %1}, %2;" : "=f"(x), "=f"(y) : "l"(v));
}
__device__ __forceinline__ void fma2(u64& d, u64 a, u64 b) {
    asm("fma.rn.f32x2 %0, %1, %2, %0;" : "+l"(d) : "l"(a), "l"(b));
}

// ---------------- step-0 gradient: g = clip(z) ----------------
__global__ void clip0_kernel(const float* __restrict__ z)
{
    int i = blockIdx.x * blockDim.x + threadIdx.x;
    if (i < BB * ZD) {
        float v = z[i];
        g_grad[i] = fminf(fmaxf(v, -100.0f), 100.0f);
    }
}

// ---------------- Encoder: warp-per-b, permuted float4 weights ----------------
// ownership c = lane + 32q; weights stored at perm(c) = 4*(c%32) + c/32 so each
// lane's 4 column-weights are one aligned conflict-free LDS.128.
#define EGPB 14
#define EGSZ 1792   /* h-tile 128*12 + xs 128 + ys 64 + ms 64 */

__global__ void __launch_bounds__(448, 1) encoder_kernel(
    const float* __restrict__ x_ctx, const float* __restrict__ y_ctx,
    const float* __restrict__ mask,
    const float* __restrict__ We1, const float* __restrict__ be1,
    const float* __restrict__ We2, const float* __restrict__ be2,
    const float* __restrict__ We3, const float* __restrict__ be3)
{
    extern __shared__ float sm[];
    float* We2s  = sm;                 // 128*128, permuted columns
    float* We3s  = We2s + HD * HD;     // 128*128, permuted columns
    float* gbase = We3s + HD * HD;

    const int tidb = threadIdx.x;
    const int grp  = tidb >> 5;
    const int lane = tidb & 31;

    float* gb  = gbase + grp * EGSZ;
    float* hT  = gb;                   // 128 rows x stride 12 (h1 then h2)
    float* xs  = gb + 1536;            // 128
    float* ys  = xs + 128;             // 64
    float* ms  = ys + 64;              // 64

    for (int i = tidb; i < HD * HD; i += 448) {
        int k = i >> 7, c = i & 127;
        int pc = 4 * (c & 31) + (c >> 5);
        We2s[k * 128 + pc] = We2[i];
        We3s[k * 128 + pc] = We3[i];
    }
    float w10[4], w11[4], w12[4], b1c[4], b2c[4], b3c[4];
    #pragma unroll
    for (int q = 0; q < 4; ++q) {
        const int c = lane + 32 * q;
        w10[q] = We1[c]; w11[q] = We1[HD + c]; w12[q] = We1[2 * HD + c];
        b1c[q] = be1[c]; b2c[q] = be2[c];      b3c[q] = be3[c];
    }
    __syncthreads();

    const int b = blockIdx.x * EGPB + grp;
    if (b >= BB) return;

    #pragma unroll
    for (int i = 0; i < 4; ++i) xs[lane + 32 * i] = x_ctx[b * (NCTX * 2) + lane + 32 * i];
    ys[lane] = y_ctx[b * NCTX + lane];  ys[lane + 32] = y_ctx[b * NCTX + lane + 32];
    ms[lane] = mask[b * NCTX + lane];   ms[lane + 32] = mask[b * NCTX + lane + 32];
    __syncwarp();

    float racc[4] = {0.0f, 0.0f, 0.0f, 0.0f};
    #pragma unroll 1
    for (int it = 0; it < NCTX / 8; ++it) {
        const int n0 = it * 8;
        // ---- h1 per owned c ----
        #pragma unroll
        for (int q = 0; q < 4; ++q) {
            float hv[8];
            #pragma unroll
            for (int n = 0; n < 8; ++n) {
                const int nn = n0 + n;
                float p = b1c[q] + xs[2 * nn] * w10[q] + xs[2 * nn + 1] * w11[q]
                        + ys[nn] * w12[q];
                hv[n] = p * sigf(p);
            }
            *(float4*)&hT[(lane + 32 * q) * 12]     = make_float4(hv[0], hv[1], hv[2], hv[3]);
            *(float4*)&hT[(lane + 32 * q) * 12 + 4] = make_float4(hv[4], hv[5], hv[6], hv[7]);
        }
        __syncwarp();

        // ---- layer 2 GEMM ----
        u64 acc[4][4];
        #pragma unroll
        for (int q = 0; q < 4; ++q)
            #pragma unroll
            for (int p = 0; p < 4; ++p) acc[q][p] = pk2(b2c[q], b2c[q]);
        #pragma unroll 4
        for (int k = 0; k < HD; ++k) {
            const float4 W = *(const float4*)&We2s[k * 128 + 4 * lane];
            const float4 HA = *(const float4*)&hT[k * 12];
            const float4 HB = *(const float4*)&hT[k * 12 + 4];
            const u64 h0 = pk2(HA.x, HA.y), h1p = pk2(HA.z, HA.w);
            const u64 h2p = pk2(HB.x, HB.y), h3p = pk2(HB.z, HB.w);
            const float* wp = (const float*)&W;
            #pragma unroll
            for (int q = 0; q < 4; ++q) {
                const u64 wd = pk2(wp[q], wp[q]);
                fma2(acc[q][0], wd, h0);  fma2(acc[q][1], wd, h1p);
                fma2(acc[q][2], wd, h2p); fma2(acc[q][3], wd, h3p);
            }
        }
        __syncwarp();   // everyone done reading h1 tile

        // ---- h2 = silu(pre2) back into tile ----
        #pragma unroll
        for (int q = 0; q < 4; ++q) {
            float a[8];
            #pragma unroll
            for (int p = 0; p < 4; ++p) up2(acc[q][p], a[2 * p], a[2 * p + 1]);
            #pragma unroll
            for (int n = 0; n < 8; ++n) a[n] = a[n] * sigf(a[n]);
            *(float4*)&hT[(lane + 32 * q) * 12]     = make_float4(a[0], a[1], a[2], a[3]);
            *(float4*)&hT[(lane + 32 * q) * 12 + 4] = make_float4(a[4], a[5], a[6], a[7]);
        }
        __syncwarp();

        // ---- layer 3 GEMM ----
        u64 ac3[4][4];
        #pragma unroll
        for (int q = 0; q < 4; ++q)
            #pragma unroll
            for (int p = 0; p < 4; ++p) ac3[q][p] = 0ull;
        #pragma unroll 4
        for (int k = 0; k < HD; ++k) {
            const float4 W = *(const float4*)&We3s[k * 128 + 4 * lane];
            const float4 HA = *(const float4*)&hT[k * 12];
            const float4 HB = *(const float4*)&hT[k * 12 + 4];
            const u64 h0 = pk2(HA.x, HA.y), h1p = pk2(HA.z, HA.w);
            const u64 h2p = pk2(HB.x, HB.y), h3p = pk2(HB.z, HB.w);
            const float* wp = (const float*)&W;
            #pragma unroll
            for (int q = 0; q < 4; ++q) {
                const u64 wd = pk2(wp[q], wp[q]);
                fma2(ac3[q][0], wd, h0);  fma2(ac3[q][1], wd, h1p);
                fma2(ac3[q][2], wd, h2p); fma2(ac3[q][3], wd, h3p);
            }
        }
        // racc += out * m  (bias folded later via msum)
        #pragma unroll
        for (int q = 0; q < 4; ++q) {
            float a[8];
            #pragma unroll
            for (int p = 0; p < 4; ++p) up2(ac3[q][p], a[2 * p], a[2 * p + 1]);
            #pragma unroll
            for (int n = 0; n < 8; ++n) racc[q] = fmaf(a[n], ms[n0 + n], racc[q]);
        }
        __syncwarp();   // tile reuse next iteration
    }

    float msum = 0.0f;
    #pragma unroll
    for (int n = 0; n < NCTX; ++n) msum += ms[n];
    const float inv = 1.0f / fmaxf(msum, 1e-6f);
    #pragma unroll
    for (int q = 0; q < 4; ++q)
        g_r[b * RD + lane + 32 * q] = (racc[q] + b3c[q] * msum) * inv;
}

// ---------------- Grad kernel (R14-passing, unchanged) ----------------
#define GPB   14
#define GSZ   1984

__global__ void __launch_bounds__(448, 1) grad_kernel(
    const float* __restrict__ z, const float* __restrict__ x_ctx,
    const float* __restrict__ y_ctx, const float* __restrict__ mask,
    const float* __restrict__ Wd1, const float* __restrict__ bd1,
    const float* __restrict__ Wd2, const float* __restrict__ bd2,
    const float* __restrict__ Wd3, const float* __restrict__ bd3,
    float t)
{
    extern __shared__ float sm[];
    float* Wd1p  = sm;
    float* Wd2p  = Wd1p + 66 * 129;
    float* gbase = Wd2p + 128 * 129 + 2;

    const int tidb = threadIdx.x;
    const int grp  = tidb >> 5;
    const int lane = tidb & 31;

    float* gb  = gbase + grp * GSZ;
    float* h1T = gb;
    float* xs  = gb + 1536;
    float* ys  = xs + 128;
    float* ms  = ys + 64;
    float* zsh = ms + 64;
    float* ds  = zsh + 64;

    for (int i = tidb; i < 66 * HD; i += 448) {
        int r = i >> 7, c = i & 127;
        Wd1p[r * 129 + c] = Wd1[i];
    }
    for (int i = tidb; i < HD * HD; i += 448) {
        int r = i >> 7, c = i & 127;
        Wd2p[r * 129 + c] = Wd2[i];
    }
    float b1c[4], b2c[4], w3c[4];
    #pragma unroll
    for (int q = 0; q < 4; ++q) {
        b1c[q] = bd1[lane + 32 * q];
        b2c[q] = bd2[lane + 32 * q];
        w3c[q] = Wd3[lane + 32 * q];
    }
    const float bd3v = bd3[0];
    __syncthreads();

    float wx0[4], wx1[4];
    #pragma unroll
    for (int q = 0; q < 4; ++q) {
        wx0[q] = Wd1p[64 * 129 + lane + 32 * q];
        wx1[q] = Wd1p[65 * 129 + lane + 32 * q];
    }

    const int b = blockIdx.x * GPB + grp;
    if (b < BB) {
        zsh[lane]      = z[b * ZD + lane];
        zsh[lane + 32] = z[b * ZD + lane + 32];
        #pragma unroll
        for (int i = 0; i < 4; ++i) xs[lane + 32 * i] = x_ctx[b * (NCTX * 2) + lane + 32 * i];
        ys[lane] = y_ctx[b * NCTX + lane];      ys[lane + 32] = y_ctx[b * NCTX + lane + 32];
        ms[lane] = mask[b * NCTX + lane];       ms[lane + 32] = mask[b * NCTX + lane + 32];
        __syncwarp();

        float pre1[4] = { b1c[0], b1c[1], b1c[2], b1c[3] };
        #pragma unroll 8
        for (int k = 0; k < ZD; ++k) {
            const float zk = zsh[k];
            #pragma unroll
            for (int q = 0; q < 4; ++q)
                pre1[q] = fmaf(zk, Wd1p[k * 129 + lane + 32 * q], pre1[q]);
        }

        float dps[4] = { 0.0f, 0.0f, 0.0f, 0.0f };
        if (t > 0.0f) {
            #pragma unroll 1
            for (int it = 0; it < NCTX / 8; ++it) {
                const int n0 = it * 8;
                float sd[4][8];
                #pragma unroll
                for (int q = 0; q < 4; ++q) {
                    float hv[8];
                    #pragma unroll
                    for (int n = 0; n < 8; ++n) {
                        const float xa = xs[2 * (n0 + n)], xb = xs[2 * (n0 + n) + 1];
                        const float p = fmaf(xa, wx0[q], fmaf(xb, wx1[q], pre1[q]));
                        const float s = sigf(p);
                        hv[n] = p * s;
                        sd[q][n] = s * (1.0f + p * (1.0f - s));
                    }
                    *(float4*)&h1T[(lane + 32 * q) * 12]     = make_float4(hv[0], hv[1], hv[2], hv[3]);
                    *(float4*)&h1T[(lane + 32 * q) * 12 + 4] = make_float4(hv[4], hv[5], hv[6], hv[7]);
                }
                __syncwarp();

                u64 acc[4][4];
                #pragma unroll
                for (int q = 0; q < 4; ++q)
                    #pragma unroll
                    for (int p = 0; p < 4; ++p) acc[q][p] = pk2(b2c[q], b2c[q]);
                #pragma unroll 4
                for (int k = 0; k < HD; ++k) {
                    const float4 HA = *(const float4*)&h1T[k * 12];
                    const float4 HB = *(const float4*)&h1T[k * 12 + 4];
                    const u64 h0 = pk2(HA.x, HA.y), h1p = pk2(HA.z, HA.w);
                    const u64 h2p = pk2(HB.x, HB.y), h3p = pk2(HB.z, HB.w);
                    #pragma unroll
                    for (int q = 0; q < 4; ++q) {
                        const float w = Wd2p[k * 129 + lane + 32 * q];
                        const u64 wd = pk2(w, w);
                        fma2(acc[q][0], wd, h0);  fma2(acc[q][1], wd, h1p);
                        fma2(acc[q][2], wd, h2p); fma2(acc[q][3], wd, h3p);
                    }
                }
                float a[4][8], tder[4][8], part[8];
                #pragma unroll
                for (int n = 0; n < 8; ++n) part[n] = 0.0f;
                #pragma unroll
                for (int q = 0; q < 4; ++q) {
                    #pragma unroll
                    for (int p = 0; p < 4; ++p) up2(acc[q][p], a[q][2 * p], a[q][2 * p + 1]);
                    #pragma unroll
                    for (int n = 0; n < 8; ++n) {
                        const float s = sigf(a[q][n]);
                        part[n] = fmaf(a[q][n] * s, w3c[q], part[n]);
                        tder[q][n] = s * (1.0f + a[q][n] * (1.0f - s));
                    }
                }
                #pragma unroll
                for (int off = 16; off; off >>= 1) {
                    #pragma unroll
                    for (int n = 0; n < 8; ++n)
                        part[n] += __shfl_xor_sync(0xffffffffu, part[n], off);
                }
                float e[8];
                #pragma unroll
                for (int n = 0; n < 8; ++n)
                    e[n] = -t * (ys[n0 + n] - (part[n] + bd3v)) * ms[n0 + n];
                __syncwarp();
                #pragma unroll
                for (int q = 0; q < 4; ++q) {
                    float dv[8];
                    #pragma unroll
                    for (int n = 0; n < 8; ++n) dv[n] = e[n] * w3c[q] * tder[q][n];
                    *(float4*)&h1T[(lane + 32 * q) * 12]     = make_float4(dv[0], dv[1], dv[2], dv[3]);
                    *(float4*)&h1T[(lane + 32 * q) * 12 + 4] = make_float4(dv[4], dv[5], dv[6], dv[7]);
                }
                __syncwarp();

                u64 bc[4][4];
                #pragma unroll
                for (int q = 0; q < 4; ++q)
                    #pragma unroll
                    for (int p = 0; p < 4; ++p) bc[q][p] = 0ull;
                #pragma unroll 4
                for (int k = 0; k < HD; ++k) {
                    const float4 DA = *(const float4*)&h1T[k * 12];
                    const float4 DB = *(const float4*)&h1T[k * 12 + 4];
                    const u64 d0 = pk2(DA.x, DA.y), d1 = pk2(DA.z, DA.w);
                    const u64 d2 = pk2(DB.x, DB.y), d3 = pk2(DB.z, DB.w);
                    #pragma unroll
                    for (int q = 0; q < 4; ++q) {
                        const float w = Wd2p[(lane + 32 * q) * 129 + k];
                        const u64 wd = pk2(w, w);
                        fma2(bc[q][0], wd, d0); fma2(bc[q][1], wd, d1);
                        fma2(bc[q][2], wd, d2); fma2(bc[q][3], wd, d3);
                    }
                }
                #pragma unroll
                for (int q = 0; q < 4; ++q)
                    #pragma unroll
                    for (int p = 0; p < 4; ++p) {
                        float u, v;
                        up2(bc[q][p], u, v);
                        dps[q] = fmaf(u, sd[q][2 * p], dps[q]);
                        dps[q] = fmaf(v, sd[q][2 * p + 1], dps[q]);
                    }
                __syncwarp();
            }
        }
        #pragma unroll
        for (int q = 0; q < 4; ++q) ds[lane + 32 * q] = dps[q];
        __syncwarp();
        {
            float acc0 = 0.0f, acc1 = 0.0f;
            #pragma unroll 8
            for (int j = 0; j < HD; ++j) {
                const float dj = ds[j];
                acc0 = fmaf(dj, Wd1p[lane * 129 + j], acc0);
                acc1 = fmaf(dj, Wd1p[(lane + 32) * 129 + j], acc1);
            }
            float g0 = zsh[lane] + acc0;
            float g1 = zsh[lane + 32] + acc1;
            g0 = fminf(fmaxf(g0, -100.0f), 100.0f);
            g1 = fminf(fmaxf(g1, -100.0f), 100.0f);
            g_grad[b * ZD + lane]      = g0;
            g_grad[b * ZD + lane + 32] = g1;
        }
    }
}

// ---------------- Drift + z update (R14-passing, unchanged) ----------------
__global__ void __launch_bounds__(256, 1) drift_kernel(
    float* __restrict__ z, const float* __restrict__ noise,
    const float* __restrict__ Wf1, const float* __restrict__ bf1,
    const float* __restrict__ Wf2, const float* __restrict__ bf2,
    const float* __restrict__ Wf3, const float* __restrict__ bf3,
    float t)
{
    extern __shared__ float sm[];
    float*  Wf1s = sm;
    float*  Wf2s = Wf1s + 193 * HD;
    float*  Wf3s = Wf2s + HD * HD;
    float4* f1sT = (float4*)(Wf3s + HD * ZD);
    float4* f2sT = f1sT + 256;
    float4* zshT = f2sT + 256;
    float4* rshT = zshT + 128;

    const int tid  = threadIdx.x;
    const int half = tid >> 7;
    const int tloc = tid & 127;
    {
        const float4* A4 = (const float4*)Wf1;
        const float4* B4 = (const float4*)Wf2;
        const float4* C4 = (const float4*)Wf3;
        float4* S1 = (float4*)Wf1s; float4* S2 = (float4*)Wf2s; float4* S3 = (float4*)Wf3s;
        for (int i = tid; i < 193 * HD / 4; i += 256) S1[i] = A4[i];
        for (int i = tid; i < HD * HD / 4; i += 256)  S2[i] = B4[i];
        for (int i = tid; i < HD * ZD / 4; i += 256)  S3[i] = C4[i];
    }
    const float b1 = bf1[tloc], b2 = bf2[tloc];
    const float bf3v = bf3[tloc & 63];
    __syncthreads();
    const float wt = Wf1s[192 * HD + tloc];
    const int kk = tloc & 63, g2 = tloc >> 6;

    float4* f1h = f1sT + half * 128;
    float4* f2h = f2sT + half * 128;
    float4* zsh = zshT + half * 64;
    float4* rsh = rshT + half * 128;

    for (int b0 = blockIdx.x * 8; b0 < BB; b0 += gridDim.x * 8) {
        const int bq = b0 + 4 * half;
        float* zf = (float*)zsh;
        float* rf = (float*)rsh;
        #pragma unroll
        for (int i = tloc; i < 4 * ZD; i += 128) {
            int q = i >> 6, k = i & 63;
            zf[k * 4 + q] = z[(bq + q) * ZD + k];
        }
        #pragma unroll
        for (int i = tloc; i < 4 * RD; i += 128) {
            int q = i >> 7, k = i & 127;
            rf[k * 4 + q] = g_r[(bq + q) * RD + k];
        }
        __syncthreads();

        const float pb = fmaf(t, wt, b1);
        float p0 = pb, p1 = pb, p2 = pb, p3 = pb;
        #pragma unroll 8
        for (int k = 0; k < ZD; ++k) {
            const float w = Wf1s[k * HD + tloc];
            const float4 v = zsh[k];
            p0 = fmaf(v.x, w, p0); p1 = fmaf(v.y, w, p1);
            p2 = fmaf(v.z, w, p2); p3 = fmaf(v.w, w, p3);
        }
        #pragma unroll 8
        for (int k = 0; k < RD; ++k) {
            const float w = Wf1s[(ZD + k) * HD + tloc];
            const float4 v = rsh[k];
            p0 = fmaf(v.x, w, p0); p1 = fmaf(v.y, w, p1);
            p2 = fmaf(v.z, w, p2); p3 = fmaf(v.w, w, p3);
        }
        f1h[tloc] = make_float4(p0 * sigf(p0), p1 * sigf(p1), p2 * sigf(p2), p3 * sigf(p3));
        __syncthreads();

        p0 = b2; p1 = b2; p2 = b2; p3 = b2;
        #pragma unroll 8
        for (int k = 0; k < HD; ++k) {
            const float w = Wf2s[k * HD + tloc];
            const float4 v = f1h[k];
            p0 = fmaf(v.x, w, p0); p1 = fmaf(v.y, w, p1);
            p2 = fmaf(v.z, w, p2); p3 = fmaf(v.w, w, p3);
        }
        f2h[tloc] = make_float4(p0 * sigf(p0), p1 * sigf(p1), p2 * sigf(p2), p3 * sigf(p3));
        __syncthreads();

        float accA = 0.0f, accB = 0.0f;
        #pragma unroll 8
        for (int j = 0; j < HD; ++j) {
            const float w = Wf3s[j * ZD + kk];
            const float4 v = f2h[j];
            const float vA = g2 ? v.y : v.x;
            const float vB = g2 ? v.w : v.z;
            accA = fmaf(vA, w, accA);
            accB = fmaf(vB, w, accB);
        }
        {
            const int qA = g2, qB = g2 + 2;
            const int bA = bq + qA, bB = bq + qB;
            z[bA * ZD + kk] = zf[kk * 4 + qA]
                + (bf3v + accA - g_grad[bA * ZD + kk]) * DT
                + DIFF * noise[bA * ZD + kk];
            z[bB * ZD + kk] = zf[kk * 4 + qB]
                + (bf3v + accB - g_grad[bB * ZD + kk]) * DT
                + DIFF * noise[bB * ZD + kk];
        }
        __syncthreads();
    }
}

// ---------------------------------------------------------------------------
extern "C" void kernel_launch(void* const* d_in, const int* in_sizes, int n_in,
                              void* d_out, int out_size)
{
    const float* x_ctx  = (const float*)d_in[0];
    const float* y_ctx  = (const float*)d_in[1];
    const float* mask   = (const float*)d_in[2];
    const float* z0     = (const float*)d_in[3];
    const float* noises = (const float*)d_in[4];
    const float* We1 = (const float*)d_in[5];  const float* be1 = (const float*)d_in[6];
    const float* We2 = (const float*)d_in[7];  const float* be2 = (const float*)d_in[8];
    const float* We3 = (const float*)d_in[9];  const float* be3 = (const float*)d_in[10];
    const float* Wd1 = (const float*)d_in[11]; const float* bd1 = (const float*)d_in[12];
    const float* Wd2 = (const float*)d_in[13]; const float* bd2 = (const float*)d_in[14];
    const float* Wd3 = (const float*)d_in[15]; const float* bd3 = (const float*)d_in[16];
    const float* Wf1 = (const float*)d_in[17]; const float* bf1 = (const float*)d_in[18];
    const float* Wf2 = (const float*)d_in[19]; const float* bf2 = (const float*)d_in[20];
    const float* Wf3 = (const float*)d_in[21]; const float* bf3 = (const float*)d_in[22];
    float* z = (float*)d_out;

    const size_t smE = (size_t)(2 * HD * HD + EGPB * EGSZ) * 4;
    const size_t smG = (size_t)(66 * 129 + 128 * 129 + 2 + GPB * GSZ) * 4;
    const size_t smF = (size_t)(193 * 128 + 128 * 128 + 128 * 64
                                + 2 * (512 + 512 + 256 + 512)) * 4;

    cudaFuncSetAttribute(encoder_kernel, cudaFuncAttributeMaxDynamicSharedMemorySize, (int)smE);
    cudaFuncSetAttribute(grad_kernel,    cudaFuncAttributeMaxDynamicSharedMemorySize, (int)smG);
    cudaFuncSetAttribute(drift_kernel,   cudaFuncAttributeMaxDynamicSharedMemorySize, (int)smF);

    cudaMemcpyAsync(z, z0, (size_t)BB * ZD * sizeof(float), cudaMemcpyDeviceToDevice);
    encoder_kernel<<<147, 448, smE>>>(x_ctx, y_ctx, mask, We1, be1, We2, be2, We3, be3);

    for (int s = 0; s < NSTEPS; ++s) {
        const float t = (float)s * DT;
        if (s == 0) {
            clip0_kernel<<<(BB * ZD + 255) / 256, 256>>>(z);
        } else {
            grad_kernel<<<147, 448, smG>>>(z, x_ctx, y_ctx, mask,
                                           Wd1, bd1, Wd2, bd2, Wd3, bd3, t);
        }
        drift_kernel<<<148, 256, smF>>>(z, noises + (size_t)s * BB * ZD,
                                        Wf1, bf1, Wf2, bf2, Wf3, bf3, t);
    }
}